// round 6
// baseline (speedup 1.0000x reference)
#include <cuda_runtime.h>
#include <cuda_bf16.h>
#include <stdint.h>
#include <math.h>

// GramSchmidt: x[8,32,128,1024] fp32.
// G = X X^T per (b,c); fused (P=L*G, L) recurrence in Gram space; Q = L X;
// out = Q * rsqrt(colsumsq_over_N(Q)).

#define NBC 256
#define NV  128
#define DD  1024

__device__ float g_G[NBC * NV * NV];
__device__ float g_L[NBC * NV * NV];

__device__ __forceinline__ void cp_async16(uint32_t sa, const void* g) {
    asm volatile("cp.async.cg.shared.global [%0], [%1], 16;\n" :: "r"(sa), "l"(g));
}
#define CP_COMMIT()  asm volatile("cp.async.commit_group;\n" ::: "memory")
#define CP_WAIT(n)   asm volatile("cp.async.wait_group %0;\n" :: "n"(n) : "memory")

__device__ __forceinline__ void fma2(unsigned long long& d,
                                     unsigned long long a, unsigned long long b) {
    asm volatile("fma.rn.f32x2 %0, %1, %2, %0;" : "+l"(d) : "l"(a), "l"(b));
}

// ---------------------------------------------------------------- kernel A
// G[bc] = X X^T. 256 thr, 8x8/thread, f32x2 FMA (pairs over k), cp.async
// 3-stage ring of 64-col chunks.
__global__ void gs_gram_kernel(const float* __restrict__ X) {
    extern __shared__ float4 sm4[];               // 3 x [128 rows][16 f4] swizzled
    const int bc = blockIdx.x;
    const float* Xb = X + (size_t)bc * (NV * DD);
    const int t  = threadIdx.x;
    const int tx = t & 15;
    const int ty = t >> 4;
    const uint32_t sbase = (uint32_t)__cvta_generic_to_shared(sm4);

    unsigned long long acc[8][8];
#pragma unroll
    for (int m = 0; m < 8; m++)
#pragma unroll
        for (int n = 0; n < 8; n++) acc[m][n] = 0ull;

    // prologue: chunks 0,1
#pragma unroll
    for (int pc = 0; pc < 2; pc++) {
#pragma unroll
        for (int it = 0; it < 8; it++) {
            int fl = t + 256 * it;                // 0..2047
            int r = fl >> 4, c4 = fl & 15;
            cp_async16(sbase + (uint32_t)((pc * 2048 + r * 16 + ((c4 + (r >> 3)) & 15)) * 16),
                       Xb + r * DD + pc * 64 + c4 * 4);
        }
        CP_COMMIT();
    }

    for (int ch = 0; ch < 16; ch++) {
        if (ch + 2 < 16) {
            int buf = (ch + 2) % 3;
#pragma unroll
            for (int it = 0; it < 8; it++) {
                int fl = t + 256 * it;
                int r = fl >> 4, c4 = fl & 15;
                cp_async16(sbase + (uint32_t)((buf * 2048 + r * 16 + ((c4 + (r >> 3)) & 15)) * 16),
                           Xb + r * DD + (ch + 2) * 64 + c4 * 4);
            }
            CP_COMMIT();
            CP_WAIT(2);
        } else if (ch + 1 < 16) {
            CP_WAIT(1);
        } else {
            CP_WAIT(0);
        }
        __syncthreads();                           // chunk ch visible to all

        const uint32_t cb = sbase + (uint32_t)((ch % 3) * 2048) * 16;
#pragma unroll
        for (int k4 = 0; k4 < 16; k4++) {
            unsigned long long a2[8][2], b2[8][2];
#pragma unroll
            for (int m = 0; m < 8; m++) {
                int r = ty * 8 + m;
                uint32_t sa = cb + (uint32_t)((r * 16 + ((k4 + ty) & 15)) * 16);
                asm volatile("ld.shared.v2.u64 {%0,%1}, [%2];"
                             : "=l"(a2[m][0]), "=l"(a2[m][1]) : "r"(sa));
            }
#pragma unroll
            for (int n = 0; n < 8; n++) {
                int r = tx * 8 + n;
                uint32_t sa = cb + (uint32_t)((r * 16 + ((k4 + tx) & 15)) * 16);
                asm volatile("ld.shared.v2.u64 {%0,%1}, [%2];"
                             : "=l"(b2[n][0]), "=l"(b2[n][1]) : "r"(sa));
            }
#pragma unroll
            for (int m = 0; m < 8; m++)
#pragma unroll
                for (int n = 0; n < 8; n++) {
                    fma2(acc[m][n], a2[m][0], b2[n][0]);
                    fma2(acc[m][n], a2[m][1], b2[n][1]);
                }
        }
        __syncthreads();                           // done reading buf before reuse
    }

    float* Gb = g_G + (size_t)bc * (NV * NV);
#pragma unroll
    for (int m = 0; m < 8; m++) {
        float v[8];
#pragma unroll
        for (int n = 0; n < 8; n++) {
            float lo, hi;
            asm volatile("mov.b64 {%0,%1}, %2;" : "=f"(lo), "=f"(hi) : "l"(acc[m][n]));
            v[n] = lo + hi;
        }
        *(float4*)(Gb + (ty * 8 + m) * NV + tx * 8)     = make_float4(v[0], v[1], v[2], v[3]);
        *(float4*)(Gb + (ty * 8 + m) * NV + tx * 8 + 4) = make_float4(v[4], v[5], v[6], v[7]);
    }
}

// ---------------------------------------------------------------- kernel B
// Fused (P = L G, L) recurrence. P_i = G_i - sum_j coef_j P_j,
// L_i = e_i - sum_j coef_j L_j, coef_j = P[j][i] / P[j][j]. n_i = P_i[i]
// (exact identity: P_i[k] = 0 for k < i by orthogonality).
// PL interleaved float2 (one LDS.64 feeds both FMAs), stride 129
// (conflict-free column reads). G row streamed via register prefetch.
__global__ void gs_chol_kernel() {
    extern __shared__ float2 PL[];              // 128 x 129 (P, L) pairs
    float* coef = (float*)(PL + NV * 129);      // 128

    const int bc = blockIdx.x;
    const int t  = threadIdx.x;                 // 128
    const float* Gb = g_G + (size_t)bc * (NV * NV);

    // zero PL (rows > current i must read as exact 0.0 when over-rounded)
#pragma unroll
    for (int it = 0; it < 129; it++)
        PL[it * 128 + t] = make_float2(0.f, 0.f);
    __syncthreads();

    // iteration 0
    float invnn = 1.f;
    float g0 = Gb[t];
    PL[t] = make_float2(g0, (t == 0) ? 1.f : 0.f);
    if (t == 0) invnn = 1.f / g0;
    float g_cur = Gb[NV + t];                   // row 1 prefetch
    __syncthreads();

    for (int i = 1; i < NV; i++) {
        float g_next = (i + 1 < NV) ? Gb[(i + 1) * NV + t] : 0.f;

        float c = 0.f;
        if (t < i) c = PL[t * 129 + i].x * invnn;
        coef[t] = c;
        __syncthreads();

        float aP0 = g_cur, aP1 = 0.f, aP2 = 0.f, aP3 = 0.f;
        float aL0 = (t == i) ? 1.f : 0.f, aL1 = 0.f, aL2 = 0.f, aL3 = 0.f;
        const int jmax = (i + 3) & ~3;          // coef[j>=i]==0, PL rows >=i are 0
        for (int j0 = 0; j0 < jmax; j0 += 4) {
            float4 cf = *(const float4*)(coef + j0);
            float2 v0 = PL[(j0 + 0) * 129 + t];
            float2 v1 = PL[(j0 + 1) * 129 + t];
            float2 v2 = PL[(j0 + 2) * 129 + t];
            float2 v3 = PL[(j0 + 3) * 129 + t];
            aP0 -= cf.x * v0.x; aL0 -= cf.x * v0.y;
            aP1 -= cf.y * v1.x; aL1 -= cf.y * v1.y;
            aP2 -= cf.z * v2.x; aL2 -= cf.z * v2.y;
            aP3 -= cf.w * v3.x; aL3 -= cf.w * v3.y;
        }
        float Pi = (aP0 + aP1) + (aP2 + aP3);
        float Li = (aL0 + aL1) + (aL2 + aL3);
        PL[i * 129 + t] = make_float2(Pi, Li);
        if (t == i) invnn = 1.f / Pi;           // n_i = P_i[i]
        g_cur = g_next;
        __syncthreads();
    }

    float* Lb = g_L + (size_t)bc * (NV * NV);
#pragma unroll 4
    for (int r = 0; r < NV; r++)
        Lb[r * NV + t] = PL[r * 129 + t].y;     // coalesced gmem, conflict-free lds
}

// ---------------------------------------------------------------- kernel C
// Q = L @ Xchunk (triangular), f32x2 FMA (pairs over n), then column
// sum-of-squares over N, scale, store. blockIdx = bc*8 + dchunk.
__global__ void gs_apply_kernel(const float* __restrict__ X, float* __restrict__ out) {
    extern __shared__ float smf[];
    float4* Ls4 = (float4*)smf;            // 128 x 32 f4 swizzled
    float*  Xc  = smf + NV * NV;           // 128 k x 128 d
    float*  rn  = Xc + NV * NV;            // 128

    const int bc = blockIdx.x >> 3;
    const int dc = blockIdx.x & 7;
    const int t  = threadIdx.x;
    const int tx = t & 15;
    const int ty = t >> 4;
    const uint32_t sbase = (uint32_t)__cvta_generic_to_shared(smf);

    const float* Xb = X + (size_t)bc * (NV * DD) + dc * 128;
    const float* Lb = g_L + (size_t)bc * (NV * NV);

#pragma unroll
    for (int it = 0; it < 16; it++) {
        int fl = t + 256 * it;
        int r = fl >> 5, k4 = fl & 31;
        float4 v = ((const float4*)Lb)[r * 32 + k4];
        Ls4[r * 32 + ((k4 + (r >> 3)) & 31)] = v;
    }
#pragma unroll
    for (int it = 0; it < 16; it++) {
        int fl = t + 256 * it;
        int r = fl >> 5, c4 = fl & 31;
        *(float4*)(Xc + r * 128 + c4 * 4) = *(const float4*)(Xb + r * DD + c4 * 4);
    }
    __syncthreads();

    unsigned long long acc2[8][4];
#pragma unroll
    for (int m = 0; m < 8; m++)
#pragma unroll
        for (int p = 0; p < 4; p++) acc2[m][p] = 0ull;

    const int kmax4 = 2 * ty + 2;          // rows ty*8..ty*8+7 need k <= ty*8+7
    for (int k4 = 0; k4 < kmax4; k4++) {
        float4 a4[8];
#pragma unroll
        for (int m = 0; m < 8; m++) a4[m] = Ls4[(ty * 8 + m) * 32 + ((k4 + ty) & 31)];
#pragma unroll
        for (int kk = 0; kk < 4; kk++) {
            unsigned long long bp[4];
            uint32_t sa = sbase + (uint32_t)(NV * NV * 4) +
                          (uint32_t)(((k4 * 4 + kk) * 128 + tx * 8) * 4);
            asm volatile("ld.shared.v2.u64 {%0,%1}, [%2];"
                         : "=l"(bp[0]), "=l"(bp[1]) : "r"(sa));
            asm volatile("ld.shared.v2.u64 {%0,%1}, [%2];"
                         : "=l"(bp[2]), "=l"(bp[3]) : "r"(sa + 16));
#pragma unroll
            for (int m = 0; m < 8; m++) {
                float av = (kk == 0) ? a4[m].x : (kk == 1) ? a4[m].y
                         : (kk == 2) ? a4[m].z : a4[m].w;
                unsigned long long ap;
                asm volatile("mov.b64 %0, {%1,%1};" : "=l"(ap) : "f"(av));
                fma2(acc2[m][0], ap, bp[0]);
                fma2(acc2[m][1], ap, bp[1]);
                fma2(acc2[m][2], ap, bp[2]);
                fma2(acc2[m][3], ap, bp[3]);
            }
        }
    }
    __syncthreads();                        // everyone done reading Ls4

    float* Qs = smf;                        // reuse L region as Q staging
#pragma unroll
    for (int m = 0; m < 8; m++) {
        float v[8];
#pragma unroll
        for (int p = 0; p < 4; p++) {
            float lo, hi;
            asm volatile("mov.b64 {%0,%1}, %2;" : "=f"(lo), "=f"(hi) : "l"(acc2[m][p]));
            v[2 * p] = lo; v[2 * p + 1] = hi;
        }
        *(float4*)(Qs + (ty * 8 + m) * 128 + tx * 8)     = make_float4(v[0], v[1], v[2], v[3]);
        *(float4*)(Qs + (ty * 8 + m) * 128 + tx * 8 + 4) = make_float4(v[4], v[5], v[6], v[7]);
    }
    __syncthreads();

    if (t < 128) {
        float s = 0.f;
#pragma unroll 4
        for (int i = 0; i < 128; i++) { float q = Qs[i * 128 + t]; s += q * q; }
        rn[t] = rsqrtf(s);
    }
    __syncthreads();

    float* ob = out + (size_t)bc * (NV * DD) + dc * 128;
#pragma unroll
    for (int it = 0; it < 16; it++) {
        int fl = t + 256 * it;
        int r = fl >> 5, c4 = fl & 31;
        float4 q = *(float4*)(Qs + r * 128 + c4 * 4);
        q.x *= rn[c4 * 4 + 0];
        q.y *= rn[c4 * 4 + 1];
        q.z *= rn[c4 * 4 + 2];
        q.w *= rn[c4 * 4 + 3];
        *(float4*)(ob + r * DD + c4 * 4) = q;
    }
}

// ---------------------------------------------------------------- launcher
extern "C" void kernel_launch(void* const* d_in, const int* in_sizes, int n_in,
                              void* d_out, int out_size) {
    const float* x = (const float*)d_in[0];
    float* out = (float*)d_out;

    const int smA = 3 * 2048 * (int)sizeof(float4);                     // 98304
    const int smB = NV * 129 * (int)sizeof(float2) + NV * (int)sizeof(float); // 132608
    const int smC = (NV * NV * 2 + NV) * (int)sizeof(float);            // 131584

    cudaFuncSetAttribute(gs_gram_kernel,  cudaFuncAttributeMaxDynamicSharedMemorySize, smA);
    cudaFuncSetAttribute(gs_chol_kernel,  cudaFuncAttributeMaxDynamicSharedMemorySize, smB);
    cudaFuncSetAttribute(gs_apply_kernel, cudaFuncAttributeMaxDynamicSharedMemorySize, smC);

    gs_gram_kernel<<<NBC, 256, smA>>>(x);
    gs_chol_kernel<<<NBC, 128, smB>>>();
    gs_apply_kernel<<<NBC * 8, 256, smC>>>(x, out);
}

// round 7
// speedup vs baseline: 1.1915x; 1.1915x over previous
#include <cuda_runtime.h>
#include <cuda_bf16.h>
#include <stdint.h>
#include <math.h>

// GramSchmidt: x[8,32,128,1024] fp32.
// G = X X^T per (b,c); fused triangular-overlay (P=L*G upper, L lower-unit)
// recurrence in Gram space; Q = L X; out = Q * rsqrt(colsumsq_over_N(Q)).

#define NBC 256
#define NV  128
#define DD  1024

__device__ float g_G[NBC * NV * NV];
__device__ float g_L[NBC * NV * NV];

__device__ __forceinline__ void cp_async16(uint32_t sa, const void* g) {
    asm volatile("cp.async.cg.shared.global [%0], [%1], 16;\n" :: "r"(sa), "l"(g));
}
#define CP_COMMIT()  asm volatile("cp.async.commit_group;\n" ::: "memory")
#define CP_WAIT(n)   asm volatile("cp.async.wait_group %0;\n" :: "n"(n) : "memory")

__device__ __forceinline__ void fma2(unsigned long long& d,
                                     unsigned long long a, unsigned long long b) {
    asm volatile("fma.rn.f32x2 %0, %1, %2, %0;" : "+l"(d) : "l"(a), "l"(b));
}

// ---------------------------------------------------------------- kernel A
// G[bc] = X X^T. 256 thr, 8x8/thread, f32x2 FMA (pairs over k), cp.async
// 3-stage ring of 64-col chunks.
__global__ void gs_gram_kernel(const float* __restrict__ X) {
    extern __shared__ float4 sm4[];               // 3 x [128 rows][16 f4] swizzled
    const int bc = blockIdx.x;
    const float* Xb = X + (size_t)bc * (NV * DD);
    const int t  = threadIdx.x;
    const int tx = t & 15;
    const int ty = t >> 4;
    const uint32_t sbase = (uint32_t)__cvta_generic_to_shared(sm4);

    unsigned long long acc[8][8];
#pragma unroll
    for (int m = 0; m < 8; m++)
#pragma unroll
        for (int n = 0; n < 8; n++) acc[m][n] = 0ull;

    // prologue: chunks 0,1
#pragma unroll
    for (int pc = 0; pc < 2; pc++) {
#pragma unroll
        for (int it = 0; it < 8; it++) {
            int fl = t + 256 * it;                // 0..2047
            int r = fl >> 4, c4 = fl & 15;
            cp_async16(sbase + (uint32_t)((pc * 2048 + r * 16 + ((c4 + (r >> 3)) & 15)) * 16),
                       Xb + r * DD + pc * 64 + c4 * 4);
        }
        CP_COMMIT();
    }

    for (int ch = 0; ch < 16; ch++) {
        if (ch + 2 < 16) {
            int buf = (ch + 2) % 3;
#pragma unroll
            for (int it = 0; it < 8; it++) {
                int fl = t + 256 * it;
                int r = fl >> 4, c4 = fl & 15;
                cp_async16(sbase + (uint32_t)((buf * 2048 + r * 16 + ((c4 + (r >> 3)) & 15)) * 16),
                           Xb + r * DD + (ch + 2) * 64 + c4 * 4);
            }
            CP_COMMIT();
            CP_WAIT(2);
        } else if (ch + 1 < 16) {
            CP_WAIT(1);
        } else {
            CP_WAIT(0);
        }
        __syncthreads();                           // chunk ch visible to all

        const uint32_t cb = sbase + (uint32_t)((ch % 3) * 2048) * 16;
#pragma unroll
        for (int k4 = 0; k4 < 16; k4++) {
            unsigned long long a2[8][2], b2[8][2];
#pragma unroll
            for (int m = 0; m < 8; m++) {
                int r = ty * 8 + m;
                uint32_t sa = cb + (uint32_t)((r * 16 + ((k4 + ty) & 15)) * 16);
                asm volatile("ld.shared.v2.u64 {%0,%1}, [%2];"
                             : "=l"(a2[m][0]), "=l"(a2[m][1]) : "r"(sa));
            }
#pragma unroll
            for (int n = 0; n < 8; n++) {
                int r = tx * 8 + n;
                uint32_t sa = cb + (uint32_t)((r * 16 + ((k4 + tx) & 15)) * 16);
                asm volatile("ld.shared.v2.u64 {%0,%1}, [%2];"
                             : "=l"(b2[n][0]), "=l"(b2[n][1]) : "r"(sa));
            }
#pragma unroll
            for (int m = 0; m < 8; m++)
#pragma unroll
                for (int n = 0; n < 8; n++) {
                    fma2(acc[m][n], a2[m][0], b2[n][0]);
                    fma2(acc[m][n], a2[m][1], b2[n][1]);
                }
        }
        __syncthreads();                           // done reading buf before reuse
    }

    float* Gb = g_G + (size_t)bc * (NV * NV);
#pragma unroll
    for (int m = 0; m < 8; m++) {
        float v[8];
#pragma unroll
        for (int n = 0; n < 8; n++) {
            float lo, hi;
            asm volatile("mov.b64 {%0,%1}, %2;" : "=f"(lo), "=f"(hi) : "l"(acc[m][n]));
            v[n] = lo + hi;
        }
        *(float4*)(Gb + (ty * 8 + m) * NV + tx * 8)     = make_float4(v[0], v[1], v[2], v[3]);
        *(float4*)(Gb + (ty * 8 + m) * NV + tx * 8 + 4) = make_float4(v[4], v[5], v[6], v[7]);
    }
}

// ---------------------------------------------------------------- kernel B
// Triangular-overlay recurrence, 66.5 KB smem -> 3 CTAs/SM.
//   M[j][t] = P[j][t] (t >= j, P = L G, upper-tri, diag = n_j)
//           = L[j][t] (t <  j, L unit-lower-tri; diag 1 implicit)
//   coef_j  = P[j][i] / n_j = M[j][i] * invnn_j        (j < i)
//   P_i[t]  = G[i][t] - sum_{j<i} coef_j M[j][t]       (t >= i)
//   L_i[t]  = -coef_t - sum_{t<j<i} coef_j M[j][t]     (t <  i)
// Stride 129 -> conflict-free column reads. G row register-prefetched.
__global__ void gs_chol_kernel() {
    extern __shared__ float M[];                // 128 x 129
    float* coef = M + NV * 129;                 // 128

    const int bc = blockIdx.x;
    const int t  = threadIdx.x;                 // 128
    const int w0 = t & ~31;                     // warp's first lane id
    const float* Gb = g_G + (size_t)bc * (NV * NV);

    // zero M (tail over-reads must hit finite zeros) + coef
#pragma unroll
    for (int it = 0; it < 129; it++) M[it * 128 + t] = 0.f;
    coef[t] = 0.f;
    __syncthreads();

    // iteration 0: P row 0 = G row 0, L_0 = e_0 (implicit)
    float invnn = 1.f;
    float g0 = Gb[t];
    M[t] = g0;                                  // row 0, col t (all P region)
    if (t == 0) invnn = 1.f / g0;
    float g_cur = Gb[NV + t];                   // prefetch row 1
    __syncthreads();

    for (int i = 1; i < NV; i++) {
        float g_next = (i + 1 < NV) ? Gb[(i + 1) * NV + t] : 0.f;

        // coefficients: thread t owns invnn_t
        float c = (t < i) ? M[t * 129 + i] * invnn : 0.f;
        coef[t] = c;
        __syncthreads();

        float acc;
        if (w0 >= i) {
            // pure P warp: t >= i. acc = G[i][t] - sum_{j<i} cf_j M[j][t]
            float a0 = g_cur, a1 = 0.f, a2 = 0.f, a3 = 0.f;
            const int jmax = (i + 3) & ~3;      // coef/M rows >= i are 0 or x0
            for (int j0 = 0; j0 < jmax; j0 += 4) {
                float4 cf = *(const float4*)(coef + j0);
                a0 -= cf.x * M[(j0 + 0) * 129 + t];
                a1 -= cf.y * M[(j0 + 1) * 129 + t];
                a2 -= cf.z * M[(j0 + 2) * 129 + t];
                a3 -= cf.w * M[(j0 + 3) * 129 + t];
            }
            acc = (a0 + a1) + (a2 + a3);
        } else if (w0 + 32 <= i) {
            // pure L warp: t < i. acc = -cf_t - sum_{t<j<i} cf_j M[j][t]
            float a0 = -c, a1 = 0.f, a2 = 0.f, a3 = 0.f;
            // masked chunk j in [w0, w0+32): include only j > t
#pragma unroll
            for (int j = 0; j < 32; j += 4) {
                int jj = w0 + j;
                float m0 = (jj + 0 > t) ? coef[jj + 0] : 0.f;
                float m1 = (jj + 1 > t) ? coef[jj + 1] : 0.f;
                float m2 = (jj + 2 > t) ? coef[jj + 2] : 0.f;
                float m3 = (jj + 3 > t) ? coef[jj + 3] : 0.f;
                a0 -= m0 * M[(jj + 0) * 129 + t];
                a1 -= m1 * M[(jj + 1) * 129 + t];
                a2 -= m2 * M[(jj + 2) * 129 + t];
                a3 -= m3 * M[(jj + 3) * 129 + t];
            }
            const int jmax = (i + 3) & ~3;
            for (int j0 = w0 + 32; j0 < jmax; j0 += 4) {
                float4 cf = *(const float4*)(coef + j0);
                a0 -= cf.x * M[(j0 + 0) * 129 + t];
                a1 -= cf.y * M[(j0 + 1) * 129 + t];
                a2 -= cf.z * M[(j0 + 2) * 129 + t];
                a3 -= cf.w * M[(j0 + 3) * 129 + t];
            }
            acc = (a0 + a1) + (a2 + a3);
        } else {
            // straddling warp: lanes t < i do L, lanes t >= i do P
            bool isP = (t >= i);
            acc = isP ? g_cur : -c;
            for (int j = 0; j < w0; j++)            // only P lanes need j < w0
                acc -= (isP ? coef[j] : 0.f) * M[j * 129 + t];
            for (int j = w0; j < i; j++)            // shared range, per-lane mask
                acc -= ((isP || j > t) ? coef[j] : 0.f) * M[j * 129 + t];
        }

        M[i * 129 + t] = acc;
        if (t == i) invnn = 1.f / acc;          // n_i = P_i[i]
        g_cur = g_next;
        __syncthreads();
    }

    // writeback L: unit diag, zeros above
    float* Lb = g_L + (size_t)bc * (NV * NV);
#pragma unroll 4
    for (int r = 0; r < NV; r++) {
        float v = (t < r) ? M[r * 129 + t] : ((t == r) ? 1.f : 0.f);
        Lb[r * NV + t] = v;
    }
}

// ---------------------------------------------------------------- kernel C
// Q = L @ Xchunk (triangular), f32x2 FMA (pairs over n), then column
// sum-of-squares over N, scale, store. blockIdx = bc*8 + dchunk.
__global__ void gs_apply_kernel(const float* __restrict__ X, float* __restrict__ out) {
    extern __shared__ float smf[];
    float4* Ls4 = (float4*)smf;            // 128 x 32 f4 swizzled
    float*  Xc  = smf + NV * NV;           // 128 k x 128 d
    float*  rn  = Xc + NV * NV;            // 128

    const int bc = blockIdx.x >> 3;
    const int dc = blockIdx.x & 7;
    const int t  = threadIdx.x;
    const int tx = t & 15;
    const int ty = t >> 4;
    const uint32_t sbase = (uint32_t)__cvta_generic_to_shared(smf);

    const float* Xb = X + (size_t)bc * (NV * DD) + dc * 128;
    const float* Lb = g_L + (size_t)bc * (NV * NV);

#pragma unroll
    for (int it = 0; it < 16; it++) {
        int fl = t + 256 * it;
        int r = fl >> 5, k4 = fl & 31;
        float4 v = ((const float4*)Lb)[r * 32 + k4];
        Ls4[r * 32 + ((k4 + (r >> 3)) & 31)] = v;
    }
#pragma unroll
    for (int it = 0; it < 16; it++) {
        int fl = t + 256 * it;
        int r = fl >> 5, c4 = fl & 31;
        *(float4*)(Xc + r * 128 + c4 * 4) = *(const float4*)(Xb + r * DD + c4 * 4);
    }
    __syncthreads();

    unsigned long long acc2[8][4];
#pragma unroll
    for (int m = 0; m < 8; m++)
#pragma unroll
        for (int p = 0; p < 4; p++) acc2[m][p] = 0ull;

    const int kmax4 = 2 * ty + 2;          // rows ty*8..ty*8+7 need k <= ty*8+7
    for (int k4 = 0; k4 < kmax4; k4++) {
        float4 a4[8];
#pragma unroll
        for (int m = 0; m < 8; m++) a4[m] = Ls4[(ty * 8 + m) * 32 + ((k4 + ty) & 31)];
#pragma unroll
        for (int kk = 0; kk < 4; kk++) {
            unsigned long long bp[4];
            uint32_t sa = sbase + (uint32_t)(NV * NV * 4) +
                          (uint32_t)(((k4 * 4 + kk) * 128 + tx * 8) * 4);
            asm volatile("ld.shared.v2.u64 {%0,%1}, [%2];"
                         : "=l"(bp[0]), "=l"(bp[1]) : "r"(sa));
            asm volatile("ld.shared.v2.u64 {%0,%1}, [%2];"
                         : "=l"(bp[2]), "=l"(bp[3]) : "r"(sa + 16));
#pragma unroll
            for (int m = 0; m < 8; m++) {
                float av = (kk == 0) ? a4[m].x : (kk == 1) ? a4[m].y
                         : (kk == 2) ? a4[m].z : a4[m].w;
                unsigned long long ap;
                asm volatile("mov.b64 %0, {%1,%1};" : "=l"(ap) : "f"(av));
                fma2(acc2[m][0], ap, bp[0]);
                fma2(acc2[m][1], ap, bp[1]);
                fma2(acc2[m][2], ap, bp[2]);
                fma2(acc2[m][3], ap, bp[3]);
            }
        }
    }
    __syncthreads();                        // everyone done reading Ls4

    float* Qs = smf;                        // reuse L region as Q staging
#pragma unroll
    for (int m = 0; m < 8; m++) {
        float v[8];
#pragma unroll
        for (int p = 0; p < 4; p++) {
            float lo, hi;
            asm volatile("mov.b64 {%0,%1}, %2;" : "=f"(lo), "=f"(hi) : "l"(acc2[m][p]));
            v[2 * p] = lo; v[2 * p + 1] = hi;
        }
        *(float4*)(Qs + (ty * 8 + m) * 128 + tx * 8)     = make_float4(v[0], v[1], v[2], v[3]);
        *(float4*)(Qs + (ty * 8 + m) * 128 + tx * 8 + 4) = make_float4(v[4], v[5], v[6], v[7]);
    }
    __syncthreads();

    if (t < 128) {
        float s = 0.f;
#pragma unroll 4
        for (int i = 0; i < 128; i++) { float q = Qs[i * 128 + t]; s += q * q; }
        rn[t] = rsqrtf(s);
    }
    __syncthreads();

    float* ob = out + (size_t)bc * (NV * DD) + dc * 128;
#pragma unroll
    for (int it = 0; it < 16; it++) {
        int fl = t + 256 * it;
        int r = fl >> 5, c4 = fl & 31;
        float4 q = *(float4*)(Qs + r * 128 + c4 * 4);
        q.x *= rn[c4 * 4 + 0];
        q.y *= rn[c4 * 4 + 1];
        q.z *= rn[c4 * 4 + 2];
        q.w *= rn[c4 * 4 + 3];
        *(float4*)(ob + r * DD + c4 * 4) = q;
    }
}

// ---------------------------------------------------------------- launcher
extern "C" void kernel_launch(void* const* d_in, const int* in_sizes, int n_in,
                              void* d_out, int out_size) {
    const float* x = (const float*)d_in[0];
    float* out = (float*)d_out;

    const int smA = 3 * 2048 * (int)sizeof(float4);                     // 98304
    const int smB = (NV * 129 + NV) * (int)sizeof(float);               // 66560
    const int smC = (NV * NV * 2 + NV) * (int)sizeof(float);            // 131584

    cudaFuncSetAttribute(gs_gram_kernel,  cudaFuncAttributeMaxDynamicSharedMemorySize, smA);
    cudaFuncSetAttribute(gs_chol_kernel,  cudaFuncAttributeMaxDynamicSharedMemorySize, smB);
    cudaFuncSetAttribute(gs_apply_kernel, cudaFuncAttributeMaxDynamicSharedMemorySize, smC);

    gs_gram_kernel<<<NBC, 256, smA>>>(x);
    gs_chol_kernel<<<NBC, 128, smB>>>();
    gs_apply_kernel<<<NBC * 8, 256, smC>>>(x, out);
}

// round 9
// speedup vs baseline: 1.4679x; 1.2320x over previous
#include <cuda_runtime.h>
#include <cuda_bf16.h>
#include <stdint.h>
#include <math.h>

// GramSchmidt: x[8,32,128,1024] fp32.
// G = X X^T per (b,c) via mma.sync bf16 (hi/lo split, 3 terms, fp32 acc);
// fused triangular-overlay (P upper / L lower-unit) recurrence; Q = L X;
// out = Q * rsqrt(colsumsq_over_N(Q)).

#define NBC 256
#define NV  128
#define DD  1024

__device__ float g_G[NBC * NV * NV];
__device__ float g_L[NBC * NV * NV];

__device__ __forceinline__ uint32_t smem_u32(const void* p) {
    uint32_t a;
    asm("{ .reg .u64 t; cvta.to.shared.u64 t, %1; cvt.u32.u64 %0, t; }"
        : "=r"(a) : "l"(p));
    return a;
}

__device__ __forceinline__ void mma_bf16(float* d, uint32_t a0, uint32_t a1,
                                         uint32_t a2, uint32_t a3,
                                         uint32_t b0, uint32_t b1) {
    asm volatile(
        "mma.sync.aligned.m16n8k16.row.col.f32.bf16.bf16.f32 "
        "{%0,%1,%2,%3}, {%4,%5,%6,%7}, {%8,%9}, {%0,%1,%2,%3};"
        : "+f"(d[0]), "+f"(d[1]), "+f"(d[2]), "+f"(d[3])
        : "r"(a0), "r"(a1), "r"(a2), "r"(a3), "r"(b0), "r"(b1));
}

__device__ __forceinline__ void fma2(unsigned long long& d,
                                     unsigned long long a, unsigned long long b) {
    asm volatile("fma.rn.f32x2 %0, %1, %2, %0;" : "+l"(d) : "l"(a), "l"(b));
}

// ---------------------------------------------------------------- kernel A
// G[bc] = X X^T via HMMA bf16 hi/lo split, 3 terms (hh, hl, lh).
// 256 thr = 8 warps in 2x4 grid, warp tile 64(m) x 32(n).
// smem: 2 buffers x (hi,lo) tiles of 128 rows x 64 k, stride 72 bf16 (144 B)
//       -> fragment loads are a perfect bank permutation (conflict-free).
#define TILE_B 18432            // 128 * 144 bytes
__global__ void __launch_bounds__(256) gs_gram_mma(const float* __restrict__ X) {
    extern __shared__ __align__(16) char smc[];
    const int bc = blockIdx.x;
    const float* Xb = X + (size_t)bc * (NV * DD);
    const int t = threadIdx.x, lane = t & 31, wid = t >> 5;
    const int wm = (wid >> 2) * 64;         // warp m-origin (0 or 64)
    const int wn = (wid & 3) * 32;          // warp n-origin (0,32,64,96)
    const uint32_t sb = smem_u32(smc);

    float acc[4][4][4];
#pragma unroll
    for (int mt = 0; mt < 4; mt++)
#pragma unroll
        for (int nt = 0; nt < 4; nt++)
#pragma unroll
            for (int r = 0; r < 4; r++) acc[mt][nt][r] = 0.f;

    // per-thread store slot: fl = t + 256*it -> row = fl>>4, c4 = fl&15
    float4 pf[8];
#pragma unroll
    for (int it = 0; it < 8; it++) {
        int fl = t + 256 * it;
        pf[it] = *(const float4*)(Xb + (fl >> 4) * DD + (fl & 15) * 4);
    }

    const uint32_t lane_a = (uint32_t)((lane >> 2) * 144 + (lane & 3) * 4);

    for (int ch = 0; ch < 16; ch++) {
        const uint32_t hi_s = sb + (uint32_t)(ch & 1) * (2 * TILE_B);
        const uint32_t lo_s = hi_s + TILE_B;

        // convert + store current chunk
#pragma unroll
        for (int it = 0; it < 8; it++) {
            int fl = t + 256 * it;
            int r = fl >> 4, c4 = fl & 15;
            float4 v = pf[it];
            __nv_bfloat16 hx = __float2bfloat16(v.x);
            __nv_bfloat16 hy = __float2bfloat16(v.y);
            __nv_bfloat16 hz = __float2bfloat16(v.z);
            __nv_bfloat16 hw = __float2bfloat16(v.w);
            __nv_bfloat16 lx = __float2bfloat16(v.x - __bfloat162float(hx));
            __nv_bfloat16 ly = __float2bfloat16(v.y - __bfloat162float(hy));
            __nv_bfloat16 lz = __float2bfloat16(v.z - __bfloat162float(hz));
            __nv_bfloat16 lw = __float2bfloat16(v.w - __bfloat162float(hw));
            uint32_t h01 = ((uint32_t)__bfloat16_as_ushort(hy) << 16) | __bfloat16_as_ushort(hx);
            uint32_t h23 = ((uint32_t)__bfloat16_as_ushort(hw) << 16) | __bfloat16_as_ushort(hz);
            uint32_t l01 = ((uint32_t)__bfloat16_as_ushort(ly) << 16) | __bfloat16_as_ushort(lx);
            uint32_t l23 = ((uint32_t)__bfloat16_as_ushort(lw) << 16) | __bfloat16_as_ushort(lz);
            uint32_t off = (uint32_t)(r * 144 + c4 * 8);
            asm volatile("st.shared.v2.b32 [%0], {%1,%2};"
                         :: "r"(hi_s + off), "r"(h01), "r"(h23) : "memory");
            asm volatile("st.shared.v2.b32 [%0], {%1,%2};"
                         :: "r"(lo_s + off), "r"(l01), "r"(l23) : "memory");
        }
        // prefetch next chunk while MMA runs
        if (ch + 1 < 16) {
#pragma unroll
            for (int it = 0; it < 8; it++) {
                int fl = t + 256 * it;
                pf[it] = *(const float4*)(Xb + (fl >> 4) * DD + (ch + 1) * 64 + (fl & 15) * 4);
            }
        }
        __syncthreads();

#pragma unroll
        for (int ks = 0; ks < 4; ks++) {
            const uint32_t kb = (uint32_t)(ks * 32);
            uint32_t Ah[4][4], Al[4][4], Bh[4][2], Bl[4][2];
#pragma unroll
            for (int mt = 0; mt < 4; mt++) {
                uint32_t ah = hi_s + (uint32_t)((wm + mt * 16) * 144) + kb + lane_a;
                uint32_t al = lo_s + (uint32_t)((wm + mt * 16) * 144) + kb + lane_a;
                asm volatile("ld.shared.b32 %0, [%1];"       : "=r"(Ah[mt][0]) : "r"(ah));
                asm volatile("ld.shared.b32 %0, [%1+1152];"  : "=r"(Ah[mt][1]) : "r"(ah));
                asm volatile("ld.shared.b32 %0, [%1+16];"    : "=r"(Ah[mt][2]) : "r"(ah));
                asm volatile("ld.shared.b32 %0, [%1+1168];"  : "=r"(Ah[mt][3]) : "r"(ah));
                asm volatile("ld.shared.b32 %0, [%1];"       : "=r"(Al[mt][0]) : "r"(al));
                asm volatile("ld.shared.b32 %0, [%1+1152];"  : "=r"(Al[mt][1]) : "r"(al));
                asm volatile("ld.shared.b32 %0, [%1+16];"    : "=r"(Al[mt][2]) : "r"(al));
                asm volatile("ld.shared.b32 %0, [%1+1168];"  : "=r"(Al[mt][3]) : "r"(al));
            }
#pragma unroll
            for (int nt = 0; nt < 4; nt++) {
                uint32_t bh = hi_s + (uint32_t)((wn + nt * 8) * 144) + kb + lane_a;
                uint32_t bl = lo_s + (uint32_t)((wn + nt * 8) * 144) + kb + lane_a;
                asm volatile("ld.shared.b32 %0, [%1];"    : "=r"(Bh[nt][0]) : "r"(bh));
                asm volatile("ld.shared.b32 %0, [%1+16];" : "=r"(Bh[nt][1]) : "r"(bh));
                asm volatile("ld.shared.b32 %0, [%1];"    : "=r"(Bl[nt][0]) : "r"(bl));
                asm volatile("ld.shared.b32 %0, [%1+16];" : "=r"(Bl[nt][1]) : "r"(bl));
            }
#pragma unroll
            for (int mt = 0; mt < 4; mt++)
#pragma unroll
                for (int nt = 0; nt < 4; nt++) {
                    mma_bf16(acc[mt][nt], Ah[mt][0], Ah[mt][1], Ah[mt][2], Ah[mt][3],
                             Bh[nt][0], Bh[nt][1]);
                    mma_bf16(acc[mt][nt], Ah[mt][0], Ah[mt][1], Ah[mt][2], Ah[mt][3],
                             Bl[nt][0], Bl[nt][1]);
                    mma_bf16(acc[mt][nt], Al[mt][0], Al[mt][1], Al[mt][2], Al[mt][3],
                             Bh[nt][0], Bh[nt][1]);
                }
        }
        __syncthreads();
    }

    // writeback: d0,d1 at (row, col..col+1); d2,d3 at (row+8, ...)
    float* Gb = g_G + (size_t)bc * (NV * NV);
#pragma unroll
    for (int mt = 0; mt < 4; mt++) {
        int row = wm + mt * 16 + (lane >> 2);
#pragma unroll
        for (int nt = 0; nt < 4; nt++) {
            int col = wn + nt * 8 + (lane & 3) * 2;
            *(float2*)(Gb + row * NV + col)       = make_float2(acc[mt][nt][0], acc[mt][nt][1]);
            *(float2*)(Gb + (row + 8) * NV + col) = make_float2(acc[mt][nt][2], acc[mt][nt][3]);
        }
    }
}

// ---------------------------------------------------------------- kernel B
// Triangular-overlay recurrence, 66.5 KB smem -> 3 CTAs/SM.
__global__ void gs_chol_kernel() {
    extern __shared__ float M[];                // 128 x 129
    float* coef = M + NV * 129;                 // 128

    const int bc = blockIdx.x;
    const int t  = threadIdx.x;                 // 128
    const int w0 = t & ~31;
    const float* Gb = g_G + (size_t)bc * (NV * NV);

#pragma unroll
    for (int it = 0; it < 129; it++) M[it * 128 + t] = 0.f;
    coef[t] = 0.f;
    __syncthreads();

    float invnn = 1.f;
    float g0 = Gb[t];
    M[t] = g0;
    if (t == 0) invnn = 1.f / g0;
    float g_cur = Gb[NV + t];
    __syncthreads();

    for (int i = 1; i < NV; i++) {
        float g_next = (i + 1 < NV) ? Gb[(i + 1) * NV + t] : 0.f;

        float c = (t < i) ? M[t * 129 + i] * invnn : 0.f;
        coef[t] = c;
        __syncthreads();

        float acc;
        if (w0 >= i) {
            float a0 = g_cur, a1 = 0.f, a2 = 0.f, a3 = 0.f;
            const int jmax = (i + 3) & ~3;
            for (int j0 = 0; j0 < jmax; j0 += 4) {
                float4 cf = *(const float4*)(coef + j0);
                a0 -= cf.x * M[(j0 + 0) * 129 + t];
                a1 -= cf.y * M[(j0 + 1) * 129 + t];
                a2 -= cf.z * M[(j0 + 2) * 129 + t];
                a3 -= cf.w * M[(j0 + 3) * 129 + t];
            }
            acc = (a0 + a1) + (a2 + a3);
        } else if (w0 + 32 <= i) {
            float a0 = -c, a1 = 0.f, a2 = 0.f, a3 = 0.f;
#pragma unroll
            for (int j = 0; j < 32; j += 4) {
                int jj = w0 + j;
                float m0 = (jj + 0 > t) ? coef[jj + 0] : 0.f;
                float m1 = (jj + 1 > t) ? coef[jj + 1] : 0.f;
                float m2 = (jj + 2 > t) ? coef[jj + 2] : 0.f;
                float m3 = (jj + 3 > t) ? coef[jj + 3] : 0.f;
                a0 -= m0 * M[(jj + 0) * 129 + t];
                a1 -= m1 * M[(jj + 1) * 129 + t];
                a2 -= m2 * M[(jj + 2) * 129 + t];
                a3 -= m3 * M[(jj + 3) * 129 + t];
            }
            const int jmax = (i + 3) & ~3;
            for (int j0 = w0 + 32; j0 < jmax; j0 += 4) {
                float4 cf = *(const float4*)(coef + j0);
                a0 -= cf.x * M[(j0 + 0) * 129 + t];
                a1 -= cf.y * M[(j0 + 1) * 129 + t];
                a2 -= cf.z * M[(j0 + 2) * 129 + t];
                a3 -= cf.w * M[(j0 + 3) * 129 + t];
            }
            acc = (a0 + a1) + (a2 + a3);
        } else {
            bool isP = (t >= i);
            acc = isP ? g_cur : -c;
            for (int j = 0; j < w0; j++)
                acc -= (isP ? coef[j] : 0.f) * M[j * 129 + t];
            for (int j = w0; j < i; j++)
                acc -= ((isP || j > t) ? coef[j] : 0.f) * M[j * 129 + t];
        }

        M[i * 129 + t] = acc;
        if (t == i) invnn = 1.f / acc;
        g_cur = g_next;
        __syncthreads();
    }

    float* Lb = g_L + (size_t)bc * (NV * NV);
#pragma unroll 4
    for (int r = 0; r < NV; r++) {
        float v = (t < r) ? M[r * 129 + t] : ((t == r) ? 1.f : 0.f);
        Lb[r * NV + t] = v;
    }
}

// ---------------------------------------------------------------- kernel C
// Q = L @ Xchunk (triangular), f32x2 FMA, column sum-of-squares, scale, store.
__global__ void gs_apply_kernel(const float* __restrict__ X, float* __restrict__ out) {
    extern __shared__ float smf[];
    float4* Ls4 = (float4*)smf;            // 128 x 32 f4 swizzled
    float*  Xc  = smf + NV * NV;           // 128 k x 128 d
    float*  rn  = Xc + NV * NV;            // 128

    const int bc = blockIdx.x >> 3;
    const int dc = blockIdx.x & 7;
    const int t  = threadIdx.x;
    const int tx = t & 15;
    const int ty = t >> 4;
    const uint32_t sbase = (uint32_t)__cvta_generic_to_shared(smf);

    const float* Xb = X + (size_t)bc * (NV * DD) + dc * 128;
    const float* Lb = g_L + (size_t)bc * (NV * NV);

#pragma unroll
    for (int it = 0; it < 16; it++) {
        int fl = t + 256 * it;
        int r = fl >> 5, k4 = fl & 31;
        float4 v = ((const float4*)Lb)[r * 32 + k4];
        Ls4[r * 32 + ((k4 + (r >> 3)) & 31)] = v;
    }
#pragma unroll
    for (int it = 0; it < 16; it++) {
        int fl = t + 256 * it;
        int r = fl >> 5, c4 = fl & 31;
        *(float4*)(Xc + r * 128 + c4 * 4) = *(const float4*)(Xb + r * DD + c4 * 4);
    }
    __syncthreads();

    unsigned long long acc2[8][4];
#pragma unroll
    for (int m = 0; m < 8; m++)
#pragma unroll
        for (int p = 0; p < 4; p++) acc2[m][p] = 0ull;

    const int kmax4 = 2 * ty + 2;
    for (int k4 = 0; k4 < kmax4; k4++) {
        float4 a4[8];
#pragma unroll
        for (int m = 0; m < 8; m++) a4[m] = Ls4[(ty * 8 + m) * 32 + ((k4 + ty) & 31)];
#pragma unroll
        for (int kk = 0; kk < 4; kk++) {
            unsigned long long bp[4];
            uint32_t sa = sbase + (uint32_t)(NV * NV * 4) +
                          (uint32_t)(((k4 * 4 + kk) * 128 + tx * 8) * 4);
            asm volatile("ld.shared.v2.u64 {%0,%1}, [%2];"
                         : "=l"(bp[0]), "=l"(bp[1]) : "r"(sa));
            asm volatile("ld.shared.v2.u64 {%0,%1}, [%2];"
                         : "=l"(bp[2]), "=l"(bp[3]) : "r"(sa + 16));
#pragma unroll
            for (int m = 0; m < 8; m++) {
                float av = (kk == 0) ? a4[m].x : (kk == 1) ? a4[m].y
                         : (kk == 2) ? a4[m].z : a4[m].w;
                unsigned long long ap;
                asm volatile("mov.b64 %0, {%1,%1};" : "=l"(ap) : "f"(av));
                fma2(acc2[m][0], ap, bp[0]);
                fma2(acc2[m][1], ap, bp[1]);
                fma2(acc2[m][2], ap, bp[2]);
                fma2(acc2[m][3], ap, bp[3]);
            }
        }
    }
    __syncthreads();

    float* Qs = smf;
#pragma unroll
    for (int m = 0; m < 8; m++) {
        float v[8];
#pragma unroll
        for (int p = 0; p < 4; p++) {
            float lo, hi;
            asm volatile("mov.b64 {%0,%1}, %2;" : "=f"(lo), "=f"(hi) : "l"(acc2[m][p]));
            v[2 * p] = lo; v[2 * p + 1] = hi;
        }
        *(float4*)(Qs + (ty * 8 + m) * 128 + tx * 8)     = make_float4(v[0], v[1], v[2], v[3]);
        *(float4*)(Qs + (ty * 8 + m) * 128 + tx * 8 + 4) = make_float4(v[4], v[5], v[6], v[7]);
    }
    __syncthreads();

    if (t < 128) {
        float s = 0.f;
#pragma unroll 4
        for (int i = 0; i < 128; i++) { float q = Qs[i * 128 + t]; s += q * q; }
        rn[t] = rsqrtf(s);
    }
    __syncthreads();

    float* ob = out + (size_t)bc * (NV * DD) + dc * 128;
#pragma unroll
    for (int it = 0; it < 16; it++) {
        int fl = t + 256 * it;
        int r = fl >> 5, c4 = fl & 31;
        float4 q = *(float4*)(Qs + r * 128 + c4 * 4);
        q.x *= rn[c4 * 4 + 0];
        q.y *= rn[c4 * 4 + 1];
        q.z *= rn[c4 * 4 + 2];
        q.w *= rn[c4 * 4 + 3];
        *(float4*)(ob + r * DD + c4 * 4) = q;
    }
}

// ---------------------------------------------------------------- launcher
extern "C" void kernel_launch(void* const* d_in, const int* in_sizes, int n_in,
                              void* d_out, int out_size) {
    const float* x = (const float*)d_in[0];
    float* out = (float*)d_out;

    const int smA = 4 * TILE_B;                                         // 73728
    const int smB = (NV * 129 + NV) * (int)sizeof(float);               // 66560
    const int smC = (NV * NV * 2 + NV) * (int)sizeof(float);            // 131584

    cudaFuncSetAttribute(gs_gram_mma,     cudaFuncAttributeMaxDynamicSharedMemorySize, smA);
    cudaFuncSetAttribute(gs_chol_kernel,  cudaFuncAttributeMaxDynamicSharedMemorySize, smB);
    cudaFuncSetAttribute(gs_apply_kernel, cudaFuncAttributeMaxDynamicSharedMemorySize, smC);

    gs_gram_mma<<<NBC, 256, smA>>>(x);
    gs_chol_kernel<<<NBC, 128, smB>>>();
    gs_apply_kernel<<<NBC * 8, 256, smC>>>(x, out);
}

// round 10
// speedup vs baseline: 2.0821x; 1.4184x over previous
#include <cuda_runtime.h>
#include <cuda_bf16.h>
#include <stdint.h>
#include <math.h>

// GramSchmidt: x[8,32,128,1024] fp32.
// G = X X^T per (b,c) via mma.sync bf16 (hi/lo split, 3 terms, fp32 acc);
// fused triangular-overlay (P upper / L lower-unit) recurrence; Q = L X via
// mma.sync bf16 (ldmatrix.trans B); out = Q * rsqrt(colsumsq_over_N(Q)).

#define NBC 256
#define NV  128
#define DD  1024

__device__ float g_G[NBC * NV * NV];
__device__ float g_L[NBC * NV * NV];

__device__ __forceinline__ uint32_t smem_u32(const void* p) {
    uint32_t a;
    asm("{ .reg .u64 t; cvta.to.shared.u64 t, %1; cvt.u32.u64 %0, t; }"
        : "=r"(a) : "l"(p));
    return a;
}

__device__ __forceinline__ void mma_bf16(float* d, uint32_t a0, uint32_t a1,
                                         uint32_t a2, uint32_t a3,
                                         uint32_t b0, uint32_t b1) {
    asm volatile(
        "mma.sync.aligned.m16n8k16.row.col.f32.bf16.bf16.f32 "
        "{%0,%1,%2,%3}, {%4,%5,%6,%7}, {%8,%9}, {%0,%1,%2,%3};"
        : "+f"(d[0]), "+f"(d[1]), "+f"(d[2]), "+f"(d[3])
        : "r"(a0), "r"(a1), "r"(a2), "r"(a3), "r"(b0), "r"(b1));
}

__device__ __forceinline__ void bf16_split4(float4 v, uint32_t& h01, uint32_t& h23,
                                            uint32_t& l01, uint32_t& l23) {
    __nv_bfloat16 hx = __float2bfloat16(v.x), hy = __float2bfloat16(v.y);
    __nv_bfloat16 hz = __float2bfloat16(v.z), hw = __float2bfloat16(v.w);
    __nv_bfloat16 lx = __float2bfloat16(v.x - __bfloat162float(hx));
    __nv_bfloat16 ly = __float2bfloat16(v.y - __bfloat162float(hy));
    __nv_bfloat16 lz = __float2bfloat16(v.z - __bfloat162float(hz));
    __nv_bfloat16 lw = __float2bfloat16(v.w - __bfloat162float(hw));
    h01 = ((uint32_t)__bfloat16_as_ushort(hy) << 16) | __bfloat16_as_ushort(hx);
    h23 = ((uint32_t)__bfloat16_as_ushort(hw) << 16) | __bfloat16_as_ushort(hz);
    l01 = ((uint32_t)__bfloat16_as_ushort(ly) << 16) | __bfloat16_as_ushort(lx);
    l23 = ((uint32_t)__bfloat16_as_ushort(lw) << 16) | __bfloat16_as_ushort(lz);
}

// ---------------------------------------------------------------- kernel A
// G[bc] = X X^T via HMMA bf16 hi/lo split, 3 terms (hh, hl, lh).
#define TILE_B 18432            // 128 * 144 bytes
__global__ void __launch_bounds__(256) gs_gram_mma(const float* __restrict__ X) {
    extern __shared__ __align__(16) char smc[];
    const int bc = blockIdx.x;
    const float* Xb = X + (size_t)bc * (NV * DD);
    const int t = threadIdx.x, lane = t & 31, wid = t >> 5;
    const int wm = (wid >> 2) * 64;
    const int wn = (wid & 3) * 32;
    const uint32_t sb = smem_u32(smc);

    float acc[4][4][4];
#pragma unroll
    for (int mt = 0; mt < 4; mt++)
#pragma unroll
        for (int nt = 0; nt < 4; nt++)
#pragma unroll
            for (int r = 0; r < 4; r++) acc[mt][nt][r] = 0.f;

    float4 pf[8];
#pragma unroll
    for (int it = 0; it < 8; it++) {
        int fl = t + 256 * it;
        pf[it] = *(const float4*)(Xb + (fl >> 4) * DD + (fl & 15) * 4);
    }

    const uint32_t lane_a = (uint32_t)((lane >> 2) * 144 + (lane & 3) * 4);

    for (int ch = 0; ch < 16; ch++) {
        const uint32_t hi_s = sb + (uint32_t)(ch & 1) * (2 * TILE_B);
        const uint32_t lo_s = hi_s + TILE_B;
#pragma unroll
        for (int it = 0; it < 8; it++) {
            int fl = t + 256 * it;
            int r = fl >> 4, c4 = fl & 15;
            uint32_t h01, h23, l01, l23;
            bf16_split4(pf[it], h01, h23, l01, l23);
            uint32_t off = (uint32_t)(r * 144 + c4 * 8);
            asm volatile("st.shared.v2.b32 [%0], {%1,%2};"
                         :: "r"(hi_s + off), "r"(h01), "r"(h23) : "memory");
            asm volatile("st.shared.v2.b32 [%0], {%1,%2};"
                         :: "r"(lo_s + off), "r"(l01), "r"(l23) : "memory");
        }
        if (ch + 1 < 16) {
#pragma unroll
            for (int it = 0; it < 8; it++) {
                int fl = t + 256 * it;
                pf[it] = *(const float4*)(Xb + (fl >> 4) * DD + (ch + 1) * 64 + (fl & 15) * 4);
            }
        }
        __syncthreads();

#pragma unroll
        for (int ks = 0; ks < 4; ks++) {
            const uint32_t kb = (uint32_t)(ks * 32);
            uint32_t Ah[4][4], Al[4][4], Bh[4][2], Bl[4][2];
#pragma unroll
            for (int mt = 0; mt < 4; mt++) {
                uint32_t ah = hi_s + (uint32_t)((wm + mt * 16) * 144) + kb + lane_a;
                uint32_t al = lo_s + (uint32_t)((wm + mt * 16) * 144) + kb + lane_a;
                asm volatile("ld.shared.b32 %0, [%1];"       : "=r"(Ah[mt][0]) : "r"(ah));
                asm volatile("ld.shared.b32 %0, [%1+1152];"  : "=r"(Ah[mt][1]) : "r"(ah));
                asm volatile("ld.shared.b32 %0, [%1+16];"    : "=r"(Ah[mt][2]) : "r"(ah));
                asm volatile("ld.shared.b32 %0, [%1+1168];"  : "=r"(Ah[mt][3]) : "r"(ah));
                asm volatile("ld.shared.b32 %0, [%1];"       : "=r"(Al[mt][0]) : "r"(al));
                asm volatile("ld.shared.b32 %0, [%1+1152];"  : "=r"(Al[mt][1]) : "r"(al));
                asm volatile("ld.shared.b32 %0, [%1+16];"    : "=r"(Al[mt][2]) : "r"(al));
                asm volatile("ld.shared.b32 %0, [%1+1168];"  : "=r"(Al[mt][3]) : "r"(al));
            }
#pragma unroll
            for (int nt = 0; nt < 4; nt++) {
                uint32_t bh = hi_s + (uint32_t)((wn + nt * 8) * 144) + kb + lane_a;
                uint32_t bl = lo_s + (uint32_t)((wn + nt * 8) * 144) + kb + lane_a;
                asm volatile("ld.shared.b32 %0, [%1];"    : "=r"(Bh[nt][0]) : "r"(bh));
                asm volatile("ld.shared.b32 %0, [%1+16];" : "=r"(Bh[nt][1]) : "r"(bh));
                asm volatile("ld.shared.b32 %0, [%1];"    : "=r"(Bl[nt][0]) : "r"(bl));
                asm volatile("ld.shared.b32 %0, [%1+16];" : "=r"(Bl[nt][1]) : "r"(bl));
            }
#pragma unroll
            for (int mt = 0; mt < 4; mt++)
#pragma unroll
                for (int nt = 0; nt < 4; nt++) {
                    mma_bf16(acc[mt][nt], Ah[mt][0], Ah[mt][1], Ah[mt][2], Ah[mt][3],
                             Bh[nt][0], Bh[nt][1]);
                    mma_bf16(acc[mt][nt], Ah[mt][0], Ah[mt][1], Ah[mt][2], Ah[mt][3],
                             Bl[nt][0], Bl[nt][1]);
                    mma_bf16(acc[mt][nt], Al[mt][0], Al[mt][1], Al[mt][2], Al[mt][3],
                             Bh[nt][0], Bh[nt][1]);
                }
        }
        __syncthreads();
    }

    float* Gb = g_G + (size_t)bc * (NV * NV);
#pragma unroll
    for (int mt = 0; mt < 4; mt++) {
        int row = wm + mt * 16 + (lane >> 2);
#pragma unroll
        for (int nt = 0; nt < 4; nt++) {
            int col = wn + nt * 8 + (lane & 3) * 2;
            *(float2*)(Gb + row * NV + col)       = make_float2(acc[mt][nt][0], acc[mt][nt][1]);
            *(float2*)(Gb + (row + 8) * NV + col) = make_float2(acc[mt][nt][2], acc[mt][nt][3]);
        }
    }
}

// ---------------------------------------------------------------- kernel B
// Triangular-overlay recurrence, 66.5 KB smem -> 3 CTAs/SM.
__global__ void gs_chol_kernel() {
    extern __shared__ float M[];                // 128 x 129
    float* coef = M + NV * 129;                 // 128

    const int bc = blockIdx.x;
    const int t  = threadIdx.x;                 // 128
    const int w0 = t & ~31;
    const float* Gb = g_G + (size_t)bc * (NV * NV);

#pragma unroll
    for (int it = 0; it < 129; it++) M[it * 128 + t] = 0.f;
    coef[t] = 0.f;
    __syncthreads();

    float invnn = 1.f;
    float g0 = Gb[t];
    M[t] = g0;
    if (t == 0) invnn = 1.f / g0;
    float g_cur = Gb[NV + t];
    __syncthreads();

    for (int i = 1; i < NV; i++) {
        float g_next = (i + 1 < NV) ? Gb[(i + 1) * NV + t] : 0.f;

        float c = (t < i) ? M[t * 129 + i] * invnn : 0.f;
        coef[t] = c;
        __syncthreads();

        float acc;
        if (w0 >= i) {
            float a0 = g_cur, a1 = 0.f, a2 = 0.f, a3 = 0.f;
            const int jmax = (i + 3) & ~3;
            for (int j0 = 0; j0 < jmax; j0 += 4) {
                float4 cf = *(const float4*)(coef + j0);
                a0 -= cf.x * M[(j0 + 0) * 129 + t];
                a1 -= cf.y * M[(j0 + 1) * 129 + t];
                a2 -= cf.z * M[(j0 + 2) * 129 + t];
                a3 -= cf.w * M[(j0 + 3) * 129 + t];
            }
            acc = (a0 + a1) + (a2 + a3);
        } else if (w0 + 32 <= i) {
            float a0 = -c, a1 = 0.f, a2 = 0.f, a3 = 0.f;
#pragma unroll
            for (int j = 0; j < 32; j += 4) {
                int jj = w0 + j;
                float m0 = (jj + 0 > t) ? coef[jj + 0] : 0.f;
                float m1 = (jj + 1 > t) ? coef[jj + 1] : 0.f;
                float m2 = (jj + 2 > t) ? coef[jj + 2] : 0.f;
                float m3 = (jj + 3 > t) ? coef[jj + 3] : 0.f;
                a0 -= m0 * M[(jj + 0) * 129 + t];
                a1 -= m1 * M[(jj + 1) * 129 + t];
                a2 -= m2 * M[(jj + 2) * 129 + t];
                a3 -= m3 * M[(jj + 3) * 129 + t];
            }
            const int jmax = (i + 3) & ~3;
            for (int j0 = w0 + 32; j0 < jmax; j0 += 4) {
                float4 cf = *(const float4*)(coef + j0);
                a0 -= cf.x * M[(j0 + 0) * 129 + t];
                a1 -= cf.y * M[(j0 + 1) * 129 + t];
                a2 -= cf.z * M[(j0 + 2) * 129 + t];
                a3 -= cf.w * M[(j0 + 3) * 129 + t];
            }
            acc = (a0 + a1) + (a2 + a3);
        } else {
            bool isP = (t >= i);
            acc = isP ? g_cur : -c;
            for (int j = 0; j < w0; j++)
                acc -= (isP ? coef[j] : 0.f) * M[j * 129 + t];
            for (int j = w0; j < i; j++)
                acc -= ((isP || j > t) ? coef[j] : 0.f) * M[j * 129 + t];
        }

        M[i * 129 + t] = acc;
        if (t == i) invnn = 1.f / acc;
        g_cur = g_next;
        __syncthreads();
    }

    float* Lb = g_L + (size_t)bc * (NV * NV);
#pragma unroll 4
    for (int r = 0; r < NV; r++) {
        float v = (t < r) ? M[r * 129 + t] : ((t == r) ? 1.f : 0.f);
        Lb[r * NV + t] = v;
    }
}

// ---------------------------------------------------------------- kernel C
// Q = L @ Xchunk via HMMA bf16 hi/lo (3 terms). A = L (manual frags),
// B = X [k][d] via ldmatrix.x4.trans. Interleaved m-tiles (2mt+wp) balance
// the triangular k skip across warps. Epilogue: colsumsq over N, scale, store.
#define LT 18432                // 128 * 144 B  (L tile, 64 k)
#define XT 17408                // 64 * 272 B   (X tile, 128 d)
__global__ void __launch_bounds__(256) gs_apply_mma(const float* __restrict__ X,
                                                   float* __restrict__ out) {
    extern __shared__ __align__(16) char smc[];
    const int bc = blockIdx.x >> 3;
    const int dc = blockIdx.x & 7;
    const int t = threadIdx.x, lane = t & 31, wid = t >> 5;
    const int wp = wid >> 2;               // m-interleave group (0/1)
    const int wn = (wid & 3) * 32;         // n-origin
    const uint32_t sb = smem_u32(smc);
    const uint32_t Lh = sb, Ll = sb + LT, Xh = sb + 2 * LT, Xl = sb + 2 * LT + XT;

    const float* Xb = X + (size_t)bc * (NV * DD) + dc * 128;
    const float* Lb = g_L + (size_t)bc * (NV * NV);

    float acc[4][4][4];
#pragma unroll
    for (int mt = 0; mt < 4; mt++)
#pragma unroll
        for (int nt = 0; nt < 4; nt++)
#pragma unroll
            for (int r = 0; r < 4; r++) acc[mt][nt][r] = 0.f;

    const uint32_t lane_a = (uint32_t)((lane >> 2) * 144 + (lane & 3) * 4);
    const int brow = (lane & 7) + (lane & 8);          // 0..15
    const int bcol = wn + ((lane >> 4) << 3);          // +8 for upper half-warp

    for (int ch = 0; ch < 2; ch++) {
        // stage L[:, ch*64..+64] as bf16 hi/lo, stride 144 B
#pragma unroll
        for (int it = 0; it < 8; it++) {
            int fl = t + 256 * it;
            int r = fl >> 4, c4 = fl & 15;
            float4 v = *(const float4*)(Lb + r * NV + ch * 64 + c4 * 4);
            uint32_t h01, h23, l01, l23;
            bf16_split4(v, h01, h23, l01, l23);
            uint32_t off = (uint32_t)(r * 144 + c4 * 8);
            asm volatile("st.shared.v2.b32 [%0], {%1,%2};"
                         :: "r"(Lh + off), "r"(h01), "r"(h23) : "memory");
            asm volatile("st.shared.v2.b32 [%0], {%1,%2};"
                         :: "r"(Ll + off), "r"(l01), "r"(l23) : "memory");
        }
        // stage X[ch*64+k][0..128) as bf16 hi/lo, stride 272 B
#pragma unroll
        for (int it = 0; it < 8; it++) {
            int fl = t + 256 * it;
            int r = fl >> 5, c4 = fl & 31;
            float4 v = *(const float4*)(Xb + (ch * 64 + r) * DD + c4 * 4);
            uint32_t h01, h23, l01, l23;
            bf16_split4(v, h01, h23, l01, l23);
            uint32_t off = (uint32_t)(r * 272 + c4 * 8);
            asm volatile("st.shared.v2.b32 [%0], {%1,%2};"
                         :: "r"(Xh + off), "r"(h01), "r"(h23) : "memory");
            asm volatile("st.shared.v2.b32 [%0], {%1,%2};"
                         :: "r"(Xl + off), "r"(l01), "r"(l23) : "memory");
        }
        __syncthreads();

#pragma unroll
        for (int ks = 0; ks < 4; ks++) {
            const int kg = ch * 4 + ks;
            uint32_t Bh[4][2], Bl[4][2];
#pragma unroll
            for (int nb2 = 0; nb2 < 2; nb2++) {
                uint32_t ba = (uint32_t)((ks * 16 + brow) * 272 + (bcol + nb2 * 16) * 2);
                uint32_t r0, r1, r2, r3;
                asm volatile("ldmatrix.sync.aligned.m8n8.x4.trans.shared.b16 "
                             "{%0,%1,%2,%3}, [%4];"
                             : "=r"(r0), "=r"(r1), "=r"(r2), "=r"(r3) : "r"(Xh + ba));
                Bh[nb2 * 2][0] = r0; Bh[nb2 * 2][1] = r1;
                Bh[nb2 * 2 + 1][0] = r2; Bh[nb2 * 2 + 1][1] = r3;
                asm volatile("ldmatrix.sync.aligned.m8n8.x4.trans.shared.b16 "
                             "{%0,%1,%2,%3}, [%4];"
                             : "=r"(r0), "=r"(r1), "=r"(r2), "=r"(r3) : "r"(Xl + ba));
                Bl[nb2 * 2][0] = r0; Bl[nb2 * 2][1] = r1;
                Bl[nb2 * 2 + 1][0] = r2; Bl[nb2 * 2 + 1][1] = r3;
            }
#pragma unroll
            for (int mt = 0; mt < 4; mt++) {
                if (kg <= 2 * mt + wp) {               // triangular skip
                    uint32_t ah = Lh + (uint32_t)((2 * mt + wp) * 2304 + ks * 32) + lane_a;
                    uint32_t al = Ll + (uint32_t)((2 * mt + wp) * 2304 + ks * 32) + lane_a;
                    uint32_t A0, A1, A2, A3, a0, a1, a2, a3;
                    asm volatile("ld.shared.b32 %0, [%1];"      : "=r"(A0) : "r"(ah));
                    asm volatile("ld.shared.b32 %0, [%1+1152];" : "=r"(A1) : "r"(ah));
                    asm volatile("ld.shared.b32 %0, [%1+16];"   : "=r"(A2) : "r"(ah));
                    asm volatile("ld.shared.b32 %0, [%1+1168];" : "=r"(A3) : "r"(ah));
                    asm volatile("ld.shared.b32 %0, [%1];"      : "=r"(a0) : "r"(al));
                    asm volatile("ld.shared.b32 %0, [%1+1152];" : "=r"(a1) : "r"(al));
                    asm volatile("ld.shared.b32 %0, [%1+16];"   : "=r"(a2) : "r"(al));
                    asm volatile("ld.shared.b32 %0, [%1+1168];" : "=r"(a3) : "r"(al));
#pragma unroll
                    for (int nt = 0; nt < 4; nt++) {
                        mma_bf16(acc[mt][nt], A0, A1, A2, A3, Bh[nt][0], Bh[nt][1]);
                        mma_bf16(acc[mt][nt], A0, A1, A2, A3, Bl[nt][0], Bl[nt][1]);
                        mma_bf16(acc[mt][nt], a0, a1, a2, a3, Bh[nt][0], Bh[nt][1]);
                    }
                }
            }
        }
        __syncthreads();
    }

    // epilogue: stage Q, column norms over N, scale, store
    float* Qs = (float*)smc;                 // 128 x 132 fp32
    float* rn = Qs + 128 * 132;
#pragma unroll
    for (int mt = 0; mt < 4; mt++) {
        int row = (2 * mt + wp) * 16 + (lane >> 2);
#pragma unroll
        for (int nt = 0; nt < 4; nt++) {
            int col = wn + nt * 8 + (lane & 3) * 2;
            *(float2*)(Qs + row * 132 + col)       = make_float2(acc[mt][nt][0], acc[mt][nt][1]);
            *(float2*)(Qs + (row + 8) * 132 + col) = make_float2(acc[mt][nt][2], acc[mt][nt][3]);
        }
    }
    __syncthreads();

    if (t < 128) {
        float s = 0.f;
#pragma unroll 4
        for (int i = 0; i < 128; i++) { float q = Qs[i * 132 + t]; s += q * q; }
        rn[t] = rsqrtf(s);
    }
    __syncthreads();

    float* ob = out + (size_t)bc * (NV * DD) + dc * 128;
#pragma unroll
    for (int it = 0; it < 16; it++) {
        int fl = t + 256 * it;
        int r = fl >> 5, c4 = fl & 31;
        float4 q = *(float4*)(Qs + r * 132 + c4 * 4);
        q.x *= rn[c4 * 4 + 0];
        q.y *= rn[c4 * 4 + 1];
        q.z *= rn[c4 * 4 + 2];
        q.w *= rn[c4 * 4 + 3];
        *(float4*)(ob + r * DD + c4 * 4) = q;
    }
}

// ---------------------------------------------------------------- launcher
extern "C" void kernel_launch(void* const* d_in, const int* in_sizes, int n_in,
                              void* d_out, int out_size) {
    const float* x = (const float*)d_in[0];
    float* out = (float*)d_out;

    const int smA = 4 * TILE_B;                                         // 73728
    const int smB = (NV * 129 + NV) * (int)sizeof(float);               // 66560
    const int smC = 2 * LT + 2 * XT;                                    // 71680

    cudaFuncSetAttribute(gs_gram_mma,   cudaFuncAttributeMaxDynamicSharedMemorySize, smA);
    cudaFuncSetAttribute(gs_chol_kernel, cudaFuncAttributeMaxDynamicSharedMemorySize, smB);
    cudaFuncSetAttribute(gs_apply_mma,  cudaFuncAttributeMaxDynamicSharedMemorySize, smC);

    gs_gram_mma<<<NBC, 256, smA>>>(x);
    gs_chol_kernel<<<NBC, 128, smB>>>();
    gs_apply_mma<<<NBC * 8, 256, smC>>>(x, out);
}

// round 11
// speedup vs baseline: 2.2991x; 1.1042x over previous
#include <cuda_runtime.h>
#include <cuda_bf16.h>
#include <stdint.h>
#include <math.h>

// GramSchmidt: x[8,32,128,1024] fp32.
// G = X X^T per (b,c) via mma.sync bf16 (hi/lo split, 3 terms, fp32 acc);
// paired-column triangular-overlay recurrence (P upper / L lower-unit);
// Q = L X via mma.sync bf16; out = Q * rsqrt(colsumsq_over_N(Q)).

#define NBC 256
#define NV  128
#define DD  1024

__device__ float g_G[NBC * NV * NV];
__device__ float g_L[NBC * NV * NV];

__device__ __forceinline__ uint32_t smem_u32(const void* p) {
    uint32_t a;
    asm("{ .reg .u64 t; cvta.to.shared.u64 t, %1; cvt.u32.u64 %0, t; }"
        : "=r"(a) : "l"(p));
    return a;
}

__device__ __forceinline__ void mma_bf16(float* d, uint32_t a0, uint32_t a1,
                                         uint32_t a2, uint32_t a3,
                                         uint32_t b0, uint32_t b1) {
    asm volatile(
        "mma.sync.aligned.m16n8k16.row.col.f32.bf16.bf16.f32 "
        "{%0,%1,%2,%3}, {%4,%5,%6,%7}, {%8,%9}, {%0,%1,%2,%3};"
        : "+f"(d[0]), "+f"(d[1]), "+f"(d[2]), "+f"(d[3])
        : "r"(a0), "r"(a1), "r"(a2), "r"(a3), "r"(b0), "r"(b1));
}

__device__ __forceinline__ void bf16_split4(float4 v, uint32_t& h01, uint32_t& h23,
                                            uint32_t& l01, uint32_t& l23) {
    __nv_bfloat16 hx = __float2bfloat16(v.x), hy = __float2bfloat16(v.y);
    __nv_bfloat16 hz = __float2bfloat16(v.z), hw = __float2bfloat16(v.w);
    __nv_bfloat16 lx = __float2bfloat16(v.x - __bfloat162float(hx));
    __nv_bfloat16 ly = __float2bfloat16(v.y - __bfloat162float(hy));
    __nv_bfloat16 lz = __float2bfloat16(v.z - __bfloat162float(hz));
    __nv_bfloat16 lw = __float2bfloat16(v.w - __bfloat162float(hw));
    h01 = ((uint32_t)__bfloat16_as_ushort(hy) << 16) | __bfloat16_as_ushort(hx);
    h23 = ((uint32_t)__bfloat16_as_ushort(hw) << 16) | __bfloat16_as_ushort(hz);
    l01 = ((uint32_t)__bfloat16_as_ushort(ly) << 16) | __bfloat16_as_ushort(lx);
    l23 = ((uint32_t)__bfloat16_as_ushort(lw) << 16) | __bfloat16_as_ushort(lz);
}

// ---------------------------------------------------------------- kernel A
// G[bc] = X X^T via HMMA bf16 hi/lo split, 3 terms (hh, hl, lh).
#define TILE_B 18432            // 128 * 144 bytes
__global__ void __launch_bounds__(256) gs_gram_mma(const float* __restrict__ X) {
    extern __shared__ __align__(16) char smc[];
    const int bc = blockIdx.x;
    const float* Xb = X + (size_t)bc * (NV * DD);
    const int t = threadIdx.x, lane = t & 31, wid = t >> 5;
    const int wm = (wid >> 2) * 64;
    const int wn = (wid & 3) * 32;
    const uint32_t sb = smem_u32(smc);

    float acc[4][4][4];
#pragma unroll
    for (int mt = 0; mt < 4; mt++)
#pragma unroll
        for (int nt = 0; nt < 4; nt++)
#pragma unroll
            for (int r = 0; r < 4; r++) acc[mt][nt][r] = 0.f;

    float4 pf[8];
#pragma unroll
    for (int it = 0; it < 8; it++) {
        int fl = t + 256 * it;
        pf[it] = *(const float4*)(Xb + (fl >> 4) * DD + (fl & 15) * 4);
    }

    const uint32_t lane_a = (uint32_t)((lane >> 2) * 144 + (lane & 3) * 4);

    for (int ch = 0; ch < 16; ch++) {
        const uint32_t hi_s = sb + (uint32_t)(ch & 1) * (2 * TILE_B);
        const uint32_t lo_s = hi_s + TILE_B;
#pragma unroll
        for (int it = 0; it < 8; it++) {
            int fl = t + 256 * it;
            int r = fl >> 4, c4 = fl & 15;
            uint32_t h01, h23, l01, l23;
            bf16_split4(pf[it], h01, h23, l01, l23);
            uint32_t off = (uint32_t)(r * 144 + c4 * 8);
            asm volatile("st.shared.v2.b32 [%0], {%1,%2};"
                         :: "r"(hi_s + off), "r"(h01), "r"(h23) : "memory");
            asm volatile("st.shared.v2.b32 [%0], {%1,%2};"
                         :: "r"(lo_s + off), "r"(l01), "r"(l23) : "memory");
        }
        if (ch + 1 < 16) {
#pragma unroll
            for (int it = 0; it < 8; it++) {
                int fl = t + 256 * it;
                pf[it] = *(const float4*)(Xb + (fl >> 4) * DD + (ch + 1) * 64 + (fl & 15) * 4);
            }
        }
        __syncthreads();

#pragma unroll
        for (int ks = 0; ks < 4; ks++) {
            const uint32_t kb = (uint32_t)(ks * 32);
            uint32_t Ah[4][4], Al[4][4], Bh[4][2], Bl[4][2];
#pragma unroll
            for (int mt = 0; mt < 4; mt++) {
                uint32_t ah = hi_s + (uint32_t)((wm + mt * 16) * 144) + kb + lane_a;
                uint32_t al = lo_s + (uint32_t)((wm + mt * 16) * 144) + kb + lane_a;
                asm volatile("ld.shared.b32 %0, [%1];"       : "=r"(Ah[mt][0]) : "r"(ah));
                asm volatile("ld.shared.b32 %0, [%1+1152];"  : "=r"(Ah[mt][1]) : "r"(ah));
                asm volatile("ld.shared.b32 %0, [%1+16];"    : "=r"(Ah[mt][2]) : "r"(ah));
                asm volatile("ld.shared.b32 %0, [%1+1168];"  : "=r"(Ah[mt][3]) : "r"(ah));
                asm volatile("ld.shared.b32 %0, [%1];"       : "=r"(Al[mt][0]) : "r"(al));
                asm volatile("ld.shared.b32 %0, [%1+1152];"  : "=r"(Al[mt][1]) : "r"(al));
                asm volatile("ld.shared.b32 %0, [%1+16];"    : "=r"(Al[mt][2]) : "r"(al));
                asm volatile("ld.shared.b32 %0, [%1+1168];"  : "=r"(Al[mt][3]) : "r"(al));
            }
#pragma unroll
            for (int nt = 0; nt < 4; nt++) {
                uint32_t bh = hi_s + (uint32_t)((wn + nt * 8) * 144) + kb + lane_a;
                uint32_t bl = lo_s + (uint32_t)((wn + nt * 8) * 144) + kb + lane_a;
                asm volatile("ld.shared.b32 %0, [%1];"    : "=r"(Bh[nt][0]) : "r"(bh));
                asm volatile("ld.shared.b32 %0, [%1+16];" : "=r"(Bh[nt][1]) : "r"(bh));
                asm volatile("ld.shared.b32 %0, [%1];"    : "=r"(Bl[nt][0]) : "r"(bl));
                asm volatile("ld.shared.b32 %0, [%1+16];" : "=r"(Bl[nt][1]) : "r"(bl));
            }
#pragma unroll
            for (int mt = 0; mt < 4; mt++)
#pragma unroll
                for (int nt = 0; nt < 4; nt++) {
                    mma_bf16(acc[mt][nt], Ah[mt][0], Ah[mt][1], Ah[mt][2], Ah[mt][3],
                             Bh[nt][0], Bh[nt][1]);
                    mma_bf16(acc[mt][nt], Ah[mt][0], Ah[mt][1], Ah[mt][2], Ah[mt][3],
                             Bl[nt][0], Bl[nt][1]);
                    mma_bf16(acc[mt][nt], Al[mt][0], Al[mt][1], Al[mt][2], Al[mt][3],
                             Bh[nt][0], Bh[nt][1]);
                }
        }
        __syncthreads();
    }

    float* Gb = g_G + (size_t)bc * (NV * NV);
#pragma unroll
    for (int mt = 0; mt < 4; mt++) {
        int row = wm + mt * 16 + (lane >> 2);
#pragma unroll
        for (int nt = 0; nt < 4; nt++) {
            int col = wn + nt * 8 + (lane & 3) * 2;
            *(float2*)(Gb + row * NV + col)       = make_float2(acc[mt][nt][0], acc[mt][nt][1]);
            *(float2*)(Gb + (row + 8) * NV + col) = make_float2(acc[mt][nt][2], acc[mt][nt][3]);
        }
    }
}

// ---------------------------------------------------------------- kernel B
// Paired-column triangular-overlay recurrence, ~67 KB smem -> 3 CTAs/SM.
// Rows i, i+1 per outer step share ONE pass over M[j][t] (2 FMA / LDS).
// cf2_i (depends on row i) applied afterwards from registers:
//   a2 -= cf2_i * (t==i ? 1 : a1)   with pub = {invnn_i, P[i][i+1]}.
__global__ void gs_chol_kernel() {
    extern __shared__ float M[];                // 128 x 129
    float* cf1 = M + NV * 129;                  // 128
    float* cf2 = cf1 + NV;                      // 128
    float* pub = cf2 + NV;                      // 2

    const int bc = blockIdx.x;
    const int t  = threadIdx.x;                 // 128
    const int w0 = t & ~31;
    const float* Gb = g_G + (size_t)bc * (NV * NV);

#pragma unroll
    for (int it = 0; it < 129; it++) M[it * 128 + t] = 0.f;
    cf1[t] = 0.f; cf2[t] = 0.f;
    __syncthreads();

    float invnn = 1.f;                          // valid for thread t once row t done
    // row 0: P_0 = G_0
    float g0 = Gb[t];
    M[t] = g0;
    if (t == 0) { invnn = 1.f / g0; }
    __syncthreads();

    // row 1 (single step)
    {
        float g1 = Gb[NV + t];
        if (t == 0) pub[0] = M[1] * invnn;      // cf_0 = P[0][1]/n_0
        __syncthreads();
        float cf = pub[0];
        float v = (t >= 1) ? (g1 - cf * M[t]) : -cf;
        M[129 + t] = v;
        if (t == 1) invnn = 1.f / v;
        __syncthreads();
    }

    for (int i = 2; i < NV; i += 2) {
        float g1 = Gb[i * NV + t];
        float g2 = Gb[(i + 1) * NV + t];

        // coefficients for columns i and i+1 (rows < i all final)
        float c1 = (t < i) ? M[t * 129 + i] * invnn : 0.f;
        float c2 = (t < i) ? M[t * 129 + i + 1] * invnn : 0.f;   // cf2_i via pub later
        cf1[t] = c1; cf2[t] = c2;
        __syncthreads();

        float a1, a2;
        if (w0 >= i + 1) {
            // pure P for both rows (all t >= i+1)
            float p0 = g1, p1 = 0.f, q0 = g2, q1 = 0.f;
            const int jmax = (i + 3) & ~3;      // padded: cf zeros, M rows >= i zeros
            for (int j0 = 0; j0 < jmax; j0 += 4) {
                float4 f1 = *(const float4*)(cf1 + j0);
                float4 f2 = *(const float4*)(cf2 + j0);
                float m0 = M[(j0 + 0) * 129 + t];
                float m1 = M[(j0 + 1) * 129 + t];
                float m2 = M[(j0 + 2) * 129 + t];
                float m3 = M[(j0 + 3) * 129 + t];
                p0 -= f1.x * m0; q0 -= f2.x * m0;
                p1 -= f1.y * m1; q1 -= f2.y * m1;
                p0 -= f1.z * m2; q0 -= f2.z * m2;
                p1 -= f1.w * m3; q1 -= f2.w * m3;
            }
            a1 = p0 + p1; a2 = q0 + q1;
        } else if (w0 + 32 <= i) {
            // pure L for both rows (all t < i): mask j > t inside own chunk
            float p0 = -c1, p1 = 0.f, q0 = -c2, q1 = 0.f;
#pragma unroll
            for (int j = 0; j < 32; j += 2) {
                int jj = w0 + j;
                float u0 = M[(jj + 0) * 129 + t];
                float u1 = M[(jj + 1) * 129 + t];
                float f10 = (jj + 0 > t) ? cf1[jj + 0] : 0.f;
                float f20 = (jj + 0 > t) ? cf2[jj + 0] : 0.f;
                float f11 = (jj + 1 > t) ? cf1[jj + 1] : 0.f;
                float f21 = (jj + 1 > t) ? cf2[jj + 1] : 0.f;
                p0 -= f10 * u0; q0 -= f20 * u0;
                p1 -= f11 * u1; q1 -= f21 * u1;
            }
            const int jmax = (i + 3) & ~3;
            for (int j0 = w0 + 32; j0 < jmax; j0 += 4) {
                float4 f1 = *(const float4*)(cf1 + j0);
                float4 f2 = *(const float4*)(cf2 + j0);
                float m0 = M[(j0 + 0) * 129 + t];
                float m1 = M[(j0 + 1) * 129 + t];
                float m2 = M[(j0 + 2) * 129 + t];
                float m3 = M[(j0 + 3) * 129 + t];
                p0 -= f1.x * m0; q0 -= f2.x * m0;
                p1 -= f1.y * m1; q1 -= f2.y * m1;
                p0 -= f1.z * m2; q0 -= f2.z * m2;
                p1 -= f1.w * m3; q1 -= f2.w * m3;
            }
            a1 = p0 + p1; a2 = q0 + q1;
        } else {
            // straddle warp (contains t == i, maybe t == i+1): per-lane masks
            a1 = (t >= i) ? g1 : -c1;
            a2 = (t > i)  ? g2 : ((t == i) ? 0.f : -c2);
            for (int j = 0; j < i; j++) {
                float m = M[j * 129 + t];
                float f1 = ((t >= i) || (j > t)) ? cf1[j] : 0.f;
                float f2 = ((t > i)  || (j > t)) ? cf2[j] : 0.f;
                a1 -= f1 * m;
                a2 -= f2 * m;
            }
        }

        // row i complete
        M[i * 129 + t] = a1;
        if (t == i)     { invnn = 1.f / a1; pub[0] = invnn; }
        if (t == i + 1) { pub[1] = a1; }            // P[i][i+1]
        __syncthreads();

        // complete row i+1 from registers (no LDS)
        float cf2i = pub[1] * pub[0];
        a2 -= cf2i * ((t == i) ? 1.f : a1);
        M[(i + 1) * 129 + t] = a2;
        if (t == i + 1) invnn = 1.f / a2;
        __syncthreads();
    }

    // writeback L: unit diag, zeros above
    float* Lb = g_L + (size_t)bc * (NV * NV);
#pragma unroll 4
    for (int r = 0; r < NV; r++) {
        float v = (t < r) ? M[r * 129 + t] : ((t == r) ? 1.f : 0.f);
        Lb[r * NV + t] = v;
    }
}

// ---------------------------------------------------------------- kernel C
// Q = L @ Xchunk via HMMA bf16 hi/lo (3 terms). A = L (manual frags),
// B = X [k][d] via ldmatrix.x4.trans. Interleaved m-tiles (2mt+wp) balance
// the triangular k skip across warps. Epilogue: colsumsq over N, scale, store.
#define LT 18432                // 128 * 144 B  (L tile, 64 k)
#define XT 17408                // 64 * 272 B   (X tile, 128 d)
__global__ void __launch_bounds__(256) gs_apply_mma(const float* __restrict__ X,
                                                   float* __restrict__ out) {
    extern __shared__ __align__(16) char smc[];
    const int bc = blockIdx.x >> 3;
    const int dc = blockIdx.x & 7;
    const int t = threadIdx.x, lane = t & 31, wid = t >> 5;
    const int wp = wid >> 2;
    const int wn = (wid & 3) * 32;
    const uint32_t sb = smem_u32(smc);
    const uint32_t Lh = sb, Ll = sb + LT, Xh = sb + 2 * LT, Xl = sb + 2 * LT + XT;

    const float* Xb = X + (size_t)bc * (NV * DD) + dc * 128;
    const float* Lb = g_L + (size_t)bc * (NV * NV);

    float acc[4][4][4];
#pragma unroll
    for (int mt = 0; mt < 4; mt++)
#pragma unroll
        for (int nt = 0; nt < 4; nt++)
#pragma unroll
            for (int r = 0; r < 4; r++) acc[mt][nt][r] = 0.f;

    const uint32_t lane_a = (uint32_t)((lane >> 2) * 144 + (lane & 3) * 4);
    const int brow = (lane & 7) + (lane & 8);
    const int bcol = wn + ((lane >> 4) << 3);

    for (int ch = 0; ch < 2; ch++) {
#pragma unroll
        for (int it = 0; it < 8; it++) {
            int fl = t + 256 * it;
            int r = fl >> 4, c4 = fl & 15;
            float4 v = *(const float4*)(Lb + r * NV + ch * 64 + c4 * 4);
            uint32_t h01, h23, l01, l23;
            bf16_split4(v, h01, h23, l01, l23);
            uint32_t off = (uint32_t)(r * 144 + c4 * 8);
            asm volatile("st.shared.v2.b32 [%0], {%1,%2};"
                         :: "r"(Lh + off), "r"(h01), "r"(h23) : "memory");
            asm volatile("st.shared.v2.b32 [%0], {%1,%2};"
                         :: "r"(Ll + off), "r"(l01), "r"(l23) : "memory");
        }
#pragma unroll
        for (int it = 0; it < 8; it++) {
            int fl = t + 256 * it;
            int r = fl >> 5, c4 = fl & 31;
            float4 v = *(const float4*)(Xb + (ch * 64 + r) * DD + c4 * 4);
            uint32_t h01, h23, l01, l23;
            bf16_split4(v, h01, h23, l01, l23);
            uint32_t off = (uint32_t)(r * 272 + c4 * 8);
            asm volatile("st.shared.v2.b32 [%0], {%1,%2};"
                         :: "r"(Xh + off), "r"(h01), "r"(h23) : "memory");
            asm volatile("st.shared.v2.b32 [%0], {%1,%2};"
                         :: "r"(Xl + off), "r"(l01), "r"(l23) : "memory");
        }
        __syncthreads();

#pragma unroll
        for (int ks = 0; ks < 4; ks++) {
            const int kg = ch * 4 + ks;
            uint32_t Bh[4][2], Bl[4][2];
#pragma unroll
            for (int nb2 = 0; nb2 < 2; nb2++) {
                uint32_t ba = (uint32_t)((ks * 16 + brow) * 272 + (bcol + nb2 * 16) * 2);
                uint32_t r0, r1, r2, r3;
                asm volatile("ldmatrix.sync.aligned.m8n8.x4.trans.shared.b16 "
                             "{%0,%1,%2,%3}, [%4];"
                             : "=r"(r0), "=r"(r1), "=r"(r2), "=r"(r3) : "r"(Xh + ba));
                Bh[nb2 * 2][0] = r0; Bh[nb2 * 2][1] = r1;
                Bh[nb2 * 2 + 1][0] = r2; Bh[nb2 * 2 + 1][1] = r3;
                asm volatile("ldmatrix.sync.aligned.m8n8.x4.trans.shared.b16 "
                             "{%0,%1,%2,%3}, [%4];"
                             : "=r"(r0), "=r"(r1), "=r"(r2), "=r"(r3) : "r"(Xl + ba));
                Bl[nb2 * 2][0] = r0; Bl[nb2 * 2][1] = r1;
                Bl[nb2 * 2 + 1][0] = r2; Bl[nb2 * 2 + 1][1] = r3;
            }
#pragma unroll
            for (int mt = 0; mt < 4; mt++) {
                if (kg <= 2 * mt + wp) {
                    uint32_t ah = Lh + (uint32_t)((2 * mt + wp) * 2304 + ks * 32) + lane_a;
                    uint32_t al = Ll + (uint32_t)((2 * mt + wp) * 2304 + ks * 32) + lane_a;
                    uint32_t A0, A1, A2, A3, a0, a1, a2, a3;
                    asm volatile("ld.shared.b32 %0, [%1];"      : "=r"(A0) : "r"(ah));
                    asm volatile("ld.shared.b32 %0, [%1+1152];" : "=r"(A1) : "r"(ah));
                    asm volatile("ld.shared.b32 %0, [%1+16];"   : "=r"(A2) : "r"(ah));
                    asm volatile("ld.shared.b32 %0, [%1+1168];" : "=r"(A3) : "r"(ah));
                    asm volatile("ld.shared.b32 %0, [%1];"      : "=r"(a0) : "r"(al));
                    asm volatile("ld.shared.b32 %0, [%1+1152];" : "=r"(a1) : "r"(al));
                    asm volatile("ld.shared.b32 %0, [%1+16];"   : "=r"(a2) : "r"(al));
                    asm volatile("ld.shared.b32 %0, [%1+1168];" : "=r"(a3) : "r"(al));
#pragma unroll
                    for (int nt = 0; nt < 4; nt++) {
                        mma_bf16(acc[mt][nt], A0, A1, A2, A3, Bh[nt][0], Bh[nt][1]);
                        mma_bf16(acc[mt][nt], A0, A1, A2, A3, Bl[nt][0], Bl[nt][1]);
                        mma_bf16(acc[mt][nt], a0, a1, a2, a3, Bh[nt][0], Bh[nt][1]);
                    }
                }
            }
        }
        __syncthreads();
    }

    float* Qs = (float*)smc;                 // 128 x 132 fp32
    float* rn = Qs + 128 * 132;
#pragma unroll
    for (int mt = 0; mt < 4; mt++) {
        int row = (2 * mt + wp) * 16 + (lane >> 2);
#pragma unroll
        for (int nt = 0; nt < 4; nt++) {
            int col = wn + nt * 8 + (lane & 3) * 2;
            *(float2*)(Qs + row * 132 + col)       = make_float2(acc[mt][nt][0], acc[mt][nt][1]);
            *(float2*)(Qs + (row + 8) * 132 + col) = make_float2(acc[mt][nt][2], acc[mt][nt][3]);
        }
    }
    __syncthreads();

    if (t < 128) {
        float s = 0.f;
#pragma unroll 4
        for (int i = 0; i < 128; i++) { float q = Qs[i * 132 + t]; s += q * q; }
        rn[t] = rsqrtf(s);
    }
    __syncthreads();

    float* ob = out + (size_t)bc * (NV * DD) + dc * 128;
#pragma unroll
    for (int it = 0; it < 16; it++) {
        int fl = t + 256 * it;
        int r = fl >> 5, c4 = fl & 31;
        float4 q = *(float4*)(Qs + r * 132 + c4 * 4);
        q.x *= rn[c4 * 4 + 0];
        q.y *= rn[c4 * 4 + 1];
        q.z *= rn[c4 * 4 + 2];
        q.w *= rn[c4 * 4 + 3];
        *(float4*)(ob + r * DD + c4 * 4) = q;
    }
}

// ---------------------------------------------------------------- launcher
extern "C" void kernel_launch(void* const* d_in, const int* in_sizes, int n_in,
                              void* d_out, int out_size) {
    const float* x = (const float*)d_in[0];
    float* out = (float*)d_out;

    const int smA = 4 * TILE_B;                                         // 73728
    const int smB = (NV * 129 + 2 * NV + 8) * (int)sizeof(float);       // 67104
    const int smC = 2 * LT + 2 * XT;                                    // 71680

    cudaFuncSetAttribute(gs_gram_mma,    cudaFuncAttributeMaxDynamicSharedMemorySize, smA);
    cudaFuncSetAttribute(gs_chol_kernel, cudaFuncAttributeMaxDynamicSharedMemorySize, smB);
    cudaFuncSetAttribute(gs_apply_mma,   cudaFuncAttributeMaxDynamicSharedMemorySize, smC);

    gs_gram_mma<<<NBC, 256, smA>>>(x);
    gs_chol_kernel<<<NBC, 128, smB>>>();
    gs_apply_mma<<<NBC * 8, 256, smC>>>(x, out);
}